// round 13
// baseline (speedup 1.0000x reference)
#include <cuda_runtime.h>
#include <cuda_bf16.h>

// Problem constants
#define T_STEPS 4
#define BATCH   64
#define CIN     64
#define COUT    128
#define HH      32
#define WW      32
#define TAU     0.5f
#define THRESH  1.0f
#define BN_EPS  1e-5f

// Scratch: transposed weights [cin*9][cout] + folded BN affine
__device__ float g_wT[CIN * 9 * COUT];
__device__ float g_alpha[COUT];
__device__ float g_beta[COUT];
// LIF membrane state, [tile][cout-lane(8)][tid(256)] as float4 (L2-resident, 33.5 MB)
__device__ float4 g_mem[1024 * 8 * 256];

// ---------- f32x2 packed helpers ----------
__device__ __forceinline__ unsigned long long pack2(float lo, float hi) {
    unsigned long long r;
    asm("mov.b64 %0, {%1, %2};" : "=l"(r) : "f"(lo), "f"(hi));
    return r;
}
__device__ __forceinline__ void unpack2(unsigned long long v, float& lo, float& hi) {
    asm("mov.b64 {%0, %1}, %2;" : "=f"(lo), "=f"(hi) : "l"(v));
}
__device__ __forceinline__ void ffma2(unsigned long long& d,
                                      unsigned long long a,
                                      unsigned long long b) {
    asm("fma.rn.f32x2 %0, %1, %2, %3;" : "=l"(d) : "l"(a), "l"(b), "l"(d));
}

// ---------- cp.async helpers ----------
__device__ __forceinline__ void cp_async4(unsigned dst, const void* src, int bytes) {
    asm volatile("cp.async.ca.shared.global [%0], [%1], 4, %2;"
                 :: "r"(dst), "l"(src), "r"(bytes));
}
__device__ __forceinline__ void cp_async16(unsigned dst, const void* src) {
    asm volatile("cp.async.cg.shared.global [%0], [%1], 16;"
                 :: "r"(dst), "l"(src));
}
#define CP_COMMIT()  asm volatile("cp.async.commit_group;" ::: "memory")
#define CP_WAIT_0()  asm volatile("cp.async.wait_group 0;" ::: "memory")

// streaming store (evict-first: spikes are write-once)
__device__ __forceinline__ void stg_cs128(float* p, float4 v) {
    asm volatile("st.global.cs.v4.f32 [%0], {%1, %2, %3, %4};"
                 :: "l"(p), "f"(v.x), "f"(v.y), "f"(v.z), "f"(v.w) : "memory");
}

// ---------- prep: weight transpose + BN fold ----------
__global__ void prep_kernel(const float* __restrict__ w,
                            const float* __restrict__ cb,
                            const float* __restrict__ gamma,
                            const float* __restrict__ beta,
                            const float* __restrict__ mean,
                            const float* __restrict__ var) {
    int idx = blockIdx.x * blockDim.x + threadIdx.x;
    int stride = gridDim.x * blockDim.x;
    for (int i = idx; i < CIN * 9 * COUT; i += stride) {
        int co = i & (COUT - 1);
        int r  = i >> 7;
        g_wT[i] = w[co * (CIN * 9) + r];
    }
    if (idx < COUT) {
        float inv = rsqrtf(var[idx] + BN_EPS);
        float sc  = gamma[idx] * inv;
        g_alpha[idx] = sc;
        g_beta[idx]  = beta[idx] - mean[idx] * sc + cb[idx] * sc;
    }
}

// ---------- fused conv3x3 + BN + LIF (R11 + ci-level register pipeline) ----------
#define CIN_CHUNK 16
#define SX_ROWS   10
#define SX_PITCH  36
#define SX_FLOATS (CIN_CHUNK * SX_ROWS * SX_PITCH)   // 5760
#define SW_FLOATS (CIN_CHUNK * 9 * 32)               // 4608
#define BUF_FLOATS (SX_FLOATS + SW_FLOATS)           // 10368
#define AB_FLOATS  (2 * COUT)                        // 256
#define SMEM_BYTES ((2 * BUF_FLOATS + AB_FLOATS) * 4)   // 83968

#define N_CHUNKS_PER_TILE (T_STEPS * (CIN / CIN_CHUNK))   // 16
#define N_TILES  (BATCH * (COUT / 32) * (HH / 8))         // 1024
#define GRID_CTAS 888
#define EXTRA_CTAS (N_TILES - GRID_CTAS)                  // 136

__device__ __forceinline__ void decode_tile(int tile_id, int& b, int& cout0, int& h0) {
    b     = tile_id >> 4;
    int r = tile_id & 15;
    cout0 = (r >> 2) * 32;
    h0    = (r & 3) * 8;
}

// Load a ci's 3 rows (6 LDS.128) into registers.
__device__ __forceinline__ void load_rows(
    const float* __restrict__ sx, int ci, int h_loc, int w0,
    float4 ra[3], float4 rb[3]) {
    const float* xbase = &sx[ci * (SX_ROWS * SX_PITCH) + h_loc * SX_PITCH + w0];
#pragma unroll
    for (int kh = 0; kh < 3; kh++) {
        ra[kh] = *reinterpret_cast<const float4*>(xbase + kh * SX_PITCH);
        rb[kh] = *reinterpret_cast<const float4*>(xbase + kh * SX_PITCH + 4);
    }
}

// One kh's pack + 48 FFMA2. Per-output order (kh->kw->p) identical to R7/R11.
__device__ __forceinline__ void do_kh(
    const float* __restrict__ sw, int ci, int kh, int co_grp,
    const float4& rak, const float4& rbk,
    unsigned long long acc[4][4]) {
    unsigned long long xd[6];
    xd[0] = pack2(rak.x, rak.x);
    xd[1] = pack2(rak.y, rak.y);
    xd[2] = pack2(rak.z, rak.z);
    xd[3] = pack2(rak.w, rak.w);
    xd[4] = pack2(rbk.x, rbk.x);
    xd[5] = pack2(rbk.y, rbk.y);
#pragma unroll
    for (int kw = 0; kw < 3; kw++) {
        const ulonglong2* wp = reinterpret_cast<const ulonglong2*>(
            &sw[(ci * 9 + kh * 3 + kw) * 32 + co_grp * 8]);
        ulonglong2 wA = wp[0];
        ulonglong2 wB = wp[1];
        unsigned long long wq0 = wA.x, wq1 = wA.y, wq2 = wB.x, wq3 = wB.y;
#pragma unroll
        for (int p = 0; p < 4; p++) {
            ffma2(acc[0][p], wq0, xd[kw + p]);
            ffma2(acc[1][p], wq1, xd[kw + p]);
            ffma2(acc[2][p], wq2, xd[kw + p]);
            ffma2(acc[3][p], wq3, xd[kw + p]);
        }
    }
}

__global__ __launch_bounds__(256, 2)
void conv_lif_kernel(const float* __restrict__ x, float* __restrict__ out) {
    extern __shared__ __align__(16) float smem_dyn[];
    float* s_ab = smem_dyn + 2 * BUF_FLOATS;   // [0..127]=alpha, [128..255]=beta

    const int bid = blockIdx.x;
    const int ntiles = (bid < EXTRA_CTAS) ? 2 : 1;
    const int n_gc = ntiles * N_CHUNKS_PER_TILE;

    const int tid    = threadIdx.x;
    const int w_grp  = tid & 7;
    const int h_loc  = (tid >> 3) & 7;
    const int co_grp = tid >> 6;
    const int w0     = w_grp * 4;
    const int my_slot = 2 + (tid >> 5);        // warp-staggered: ci slots 2..9

    const unsigned smem_u32 = (unsigned)__cvta_generic_to_shared(smem_dyn);

    auto prefetch_share = [&](int gc) {
        const int tile_id = (gc >> 4) ? (bid + GRID_CTAS) : bid;
        int b, cout0, h0;
        decode_tile(tile_id, b, cout0, h0);
        const int tc = gc & 15;
        const int t  = tc >> 2;
        const int c0 = (tc & 3) * CIN_CHUNK;
        const int buf = gc & 1;
        const unsigned sx_base = smem_u32 + (unsigned)(buf * BUF_FLOATS) * 4u;
        const unsigned sw_base = sx_base + SX_FLOATS * 4u;
        const float* xb = x + (((t * BATCH + b) * CIN + c0) * (HH * WW));
        const unsigned c   = (unsigned)tid & 31u;
        const unsigned rg0 = (unsigned)tid >> 5;
#pragma unroll
        for (int k = 0; k < 20; k++) {
            unsigned rowg = rg0 + 8u * k;      // 0..159
            unsigned ci   = rowg / 10u;
            unsigned r    = rowg - ci * 10u;
            int gh = h0 - 1 + (int)r;
            bool valid = (unsigned)gh < (unsigned)HH;
            const float* src = xb + ci * (HH * WW) + (valid ? gh : 0) * WW + c;
            unsigned dst = sx_base +
                (unsigned)(ci * (SX_ROWS * SX_PITCH) + r * SX_PITCH + c + 1u) * 4u;
            cp_async4(dst, src, valid ? 4 : 0);
        }
        const float* wb = g_wT + c0 * 9 * COUT + cout0;
#pragma unroll
        for (int k = 0; k < 5; k++) {
            int e = tid + k * 256;
            if (e < SW_FLOATS / 4) {
                int co4 = e & 7;
                int rk  = e >> 3;
                unsigned dst = sw_base + (unsigned)(rk * 32 + co4 * 4) * 4u;
                cp_async16(dst, wb + rk * COUT + co4 * 4);
            }
        }
    };

    // ---- one-time init: alpha/beta -> smem, zero halo cols of both buffers ----
    for (int e = tid; e < COUT; e += 256) {
        s_ab[e]        = g_alpha[e];
        s_ab[COUT + e] = g_beta[e];
    }
    for (int e = tid; e < 2 * CIN_CHUNK * SX_ROWS * 2; e += 256) {  // 640
        int buf = e & 1;
        int q   = e >> 1;
        int col = (q & 1) ? 33 : 0;
        int rw  = q >> 1;
        int ci  = rw / SX_ROWS;
        int r   = rw - ci * SX_ROWS;
        smem_dyn[buf * BUF_FLOATS + ci * (SX_ROWS * SX_PITCH) + r * SX_PITCH + col] = 0.f;
    }

    unsigned long long acc[4][4];
#pragma unroll
    for (int cp = 0; cp < 4; cp++)
#pragma unroll
        for (int p = 0; p < 4; p++) acc[cp][p] = 0ULL;

    prefetch_share(0);
    CP_COMMIT();
    CP_WAIT_0();
    __syncthreads();

    for (int gc = 0; gc < n_gc; gc++) {
        const int buf = gc & 1;
        const float* sx = smem_dyn + buf * BUF_FLOATS;
        const float* sw = sx + SX_FLOATS;
        const bool have_next = (gc + 1 < n_gc);

        // ---- ci-level register pipeline: sets A/B, manual unroll-by-2 ----
        float4 raA[3], rbA[3], raB[3], rbB[3];
        load_rows(sx, 0, h_loc, w0, raA, rbA);
        for (int cb = 0; cb < CIN_CHUNK; cb += 2) {
            // ci = cb (rows in A); load cb+1 into B between kh=0 and kh=1
            do_kh(sw, cb, 0, co_grp, raA[0], rbA[0], acc);
            load_rows(sx, cb + 1, h_loc, w0, raB, rbB);
            do_kh(sw, cb, 1, co_grp, raA[1], rbA[1], acc);
            do_kh(sw, cb, 2, co_grp, raA[2], rbA[2], acc);
            if (have_next && cb == my_slot) {   // warp-uniform branch
                prefetch_share(gc + 1);
                CP_COMMIT();
            }
            // ci = cb+1 (rows in B); load cb+2 into A (guarded)
            do_kh(sw, cb + 1, 0, co_grp, raB[0], rbB[0], acc);
            if (cb + 2 < CIN_CHUNK)
                load_rows(sx, cb + 2, h_loc, w0, raA, rbA);
            do_kh(sw, cb + 1, 1, co_grp, raB[1], rbB[1], acc);
            do_kh(sw, cb + 1, 2, co_grp, raB[2], rbB[2], acc);
            if (have_next && (cb + 1) == my_slot) {
                prefetch_share(gc + 1);
                CP_COMMIT();
            }
        }

        // ---- epilogue at the end of each t-step ----
        if ((gc & 3) == 3) {
            const int tile_id = (gc >> 4) ? (bid + GRID_CTAS) : bid;
            int b, cout0, h0;
            decode_tile(tile_id, b, cout0, h0);
            const int t    = (gc >> 2) & 3;
            const int myc0 = cout0 + co_grp * 8;
            float4* mbase = g_mem + (size_t)tile_id * 8 * 256 + tid;
            float* ob = out + ((size_t)(t * BATCH + b) * COUT) * (HH * WW)
                            + (h0 + h_loc) * WW + w0;
#pragma unroll
            for (int cp = 0; cp < 4; cp++) {
                const int cl0 = 2 * cp, cl1 = 2 * cp + 1;
                const float a0 = s_ab[myc0 + cl0], b0 = s_ab[COUT + myc0 + cl0];
                const float a1 = s_ab[myc0 + cl1], b1 = s_ab[COUT + myc0 + cl1];
                float4 m0v, m1v;
                if (t > 0) {
                    m0v = mbase[cl0 * 256];
                    m1v = mbase[cl1 * 256];
                } else {
                    m0v = make_float4(0.f, 0.f, 0.f, 0.f);
                    m1v = make_float4(0.f, 0.f, 0.f, 0.f);
                }
                float* m0a = &m0v.x;
                float* m1a = &m1v.x;
                float sp0[4], sp1[4];
#pragma unroll
                for (int p = 0; p < 4; p++) {
                    float lo, hi;
                    unpack2(acc[cp][p], lo, hi);
                    float y0 = lo * a0 + b0;
                    float y1 = hi * a1 + b1;
                    float m0 = m0a[p] * TAU + y0;
                    float m1 = m1a[p] * TAU + y1;
                    float k0 = (m0 > THRESH) ? 1.f : 0.f;
                    float k1 = (m1 > THRESH) ? 1.f : 0.f;
                    m0a[p] = (k0 != 0.f) ? 0.f : m0;
                    m1a[p] = (k1 != 0.f) ? 0.f : m1;
                    sp0[p] = k0;
                    sp1[p] = k1;
                }
                stg_cs128(ob + (size_t)(myc0 + cl0) * (HH * WW),
                          make_float4(sp0[0], sp0[1], sp0[2], sp0[3]));
                stg_cs128(ob + (size_t)(myc0 + cl1) * (HH * WW),
                          make_float4(sp1[0], sp1[1], sp1[2], sp1[3]));
                if (t < T_STEPS - 1) {
                    mbase[cl0 * 256] = m0v;
                    mbase[cl1 * 256] = m1v;
                }
            }
#pragma unroll
            for (int cp = 0; cp < 4; cp++)
#pragma unroll
                for (int p = 0; p < 4; p++) acc[cp][p] = 0ULL;
        }

        if (have_next) CP_WAIT_0();
        // single barrier: publishes chunk gc+1's data AND releases buf^1 for
        // the prefetch issued during iteration gc+1.
        __syncthreads();
    }
}

extern "C" void kernel_launch(void* const* d_in, const int* in_sizes, int n_in,
                              void* d_out, int out_size) {
    (void)in_sizes; (void)n_in; (void)out_size;
    const float* x      = (const float*)d_in[0];
    const float* conv_w = (const float*)d_in[1];
    const float* conv_b = (const float*)d_in[2];
    const float* bng    = (const float*)d_in[3];
    const float* bnb    = (const float*)d_in[4];
    const float* bnm    = (const float*)d_in[5];
    const float* bnv    = (const float*)d_in[6];
    float* out = (float*)d_out;

    static int attr_done = 0;
    if (!attr_done) {
        cudaFuncSetAttribute(conv_lif_kernel,
                             cudaFuncAttributeMaxDynamicSharedMemorySize,
                             SMEM_BYTES);
        attr_done = 1;
    }

    prep_kernel<<<72, 256>>>(conv_w, conv_b, bng, bnb, bnm, bnv);

    conv_lif_kernel<<<GRID_CTAS, 256, SMEM_BYTES>>>(x, out);
}

// round 15
// speedup vs baseline: 1.0596x; 1.0596x over previous
#include <cuda_runtime.h>
#include <cuda_bf16.h>

// Problem constants
#define T_STEPS 4
#define BATCH   64
#define CIN     64
#define COUT    128
#define HH      32
#define WW      32
#define TAU     0.5f
#define THRESH  1.0f
#define BN_EPS  1e-5f

// Scratch: transposed weights [cin*9][cout] + folded BN affine
__device__ float g_wT[CIN * 9 * COUT];
__device__ float g_alpha[COUT];
__device__ float g_beta[COUT];
// LIF membrane state, [tile][cout-lane(8)][tid(256)] as float4 (L2-resident, 33.5 MB)
__device__ float4 g_mem[1024 * 8 * 256];

// ---------- f32x2 packed helpers ----------
__device__ __forceinline__ unsigned long long pack2(float lo, float hi) {
    unsigned long long r;
    asm("mov.b64 %0, {%1, %2};" : "=l"(r) : "f"(lo), "f"(hi));
    return r;
}
__device__ __forceinline__ void unpack2(unsigned long long v, float& lo, float& hi) {
    asm("mov.b64 {%0, %1}, %2;" : "=f"(lo), "=f"(hi) : "l"(v));
}
__device__ __forceinline__ void ffma2(unsigned long long& d,
                                      unsigned long long a,
                                      unsigned long long b) {
    asm("fma.rn.f32x2 %0, %1, %2, %3;" : "=l"(d) : "l"(a), "l"(b), "l"(d));
}

// ---------- cp.async helpers ----------
__device__ __forceinline__ void cp_async4(unsigned dst, const void* src, int bytes) {
    asm volatile("cp.async.ca.shared.global [%0], [%1], 4, %2;"
                 :: "r"(dst), "l"(src), "r"(bytes));
}
__device__ __forceinline__ void cp_async16(unsigned dst, const void* src) {
    asm volatile("cp.async.cg.shared.global [%0], [%1], 16;"
                 :: "r"(dst), "l"(src));
}
#define CP_COMMIT()  asm volatile("cp.async.commit_group;" ::: "memory")
#define CP_WAIT_0()  asm volatile("cp.async.wait_group 0;" ::: "memory")

// streaming store (evict-first: spikes are write-once)
__device__ __forceinline__ void stg_cs128(float* p, float4 v) {
    asm volatile("st.global.cs.v4.f32 [%0], {%1, %2, %3, %4};"
                 :: "l"(p), "f"(v.x), "f"(v.y), "f"(v.z), "f"(v.w) : "memory");
}

// ---------- prep: weight transpose + BN fold ----------
__global__ void prep_kernel(const float* __restrict__ w,
                            const float* __restrict__ cb,
                            const float* __restrict__ gamma,
                            const float* __restrict__ beta,
                            const float* __restrict__ mean,
                            const float* __restrict__ var) {
    int idx = blockIdx.x * blockDim.x + threadIdx.x;
    int stride = gridDim.x * blockDim.x;
    for (int i = idx; i < CIN * 9 * COUT; i += stride) {
        int co = i & (COUT - 1);
        int r  = i >> 7;
        g_wT[i] = w[co * (CIN * 9) + r];
    }
    if (idx < COUT) {
        float inv = rsqrtf(var[idx] + BN_EPS);
        float sc  = gamma[idx] * inv;
        g_alpha[idx] = sc;
        g_beta[idx]  = beta[idx] - mean[idx] * sc + cb[idx] * sc;
    }
}

// ---------- fused conv3x3 + BN + LIF (R11 loop + membrane offload) ----------
#define CIN_CHUNK 16
#define SX_ROWS   10
#define SX_PITCH  36
#define SX_FLOATS (CIN_CHUNK * SX_ROWS * SX_PITCH)   // 5760
#define SW_FLOATS (CIN_CHUNK * 9 * 32)               // 4608
#define BUF_FLOATS (SX_FLOATS + SW_FLOATS)           // 10368
#define AB_FLOATS  (2 * COUT)                        // 256
#define SMEM_BYTES ((2 * BUF_FLOATS + AB_FLOATS) * 4)   // 83968

#define N_CHUNKS_PER_TILE (T_STEPS * (CIN / CIN_CHUNK))   // 16
#define N_TILES  (BATCH * (COUT / 32) * (HH / 8))         // 1024
#define GRID_CTAS 888
#define EXTRA_CTAS (N_TILES - GRID_CTAS)                  // 136

__device__ __forceinline__ void decode_tile(int tile_id, int& b, int& cout0, int& h0) {
    b     = tile_id >> 4;
    int r = tile_id & 15;
    cout0 = (r >> 2) * 32;
    h0    = (r & 3) * 8;
}

// One ci of accumulation, all 3 rows' x loads hoisted to the top.
// Per-output accumulation order (kh -> kw -> p) identical to R7/R11.
__device__ __forceinline__ void compute_ci(
    const float* __restrict__ sx, const float* __restrict__ sw,
    int ci, int h_loc, int w0, int co_grp,
    unsigned long long acc[4][4]) {
    const float* xbase =
        &sx[ci * (SX_ROWS * SX_PITCH) + h_loc * SX_PITCH + w0];
    // 6 independent LDS.128 issued back-to-back: rows kh=0,1,2
    float4 ra[3], rb[3];
#pragma unroll
    for (int kh = 0; kh < 3; kh++) {
        ra[kh] = *reinterpret_cast<const float4*>(xbase + kh * SX_PITCH);
        rb[kh] = *reinterpret_cast<const float4*>(xbase + kh * SX_PITCH + 4);
    }
#pragma unroll
    for (int kh = 0; kh < 3; kh++) {
        unsigned long long xd[6];
        xd[0] = pack2(ra[kh].x, ra[kh].x);
        xd[1] = pack2(ra[kh].y, ra[kh].y);
        xd[2] = pack2(ra[kh].z, ra[kh].z);
        xd[3] = pack2(ra[kh].w, ra[kh].w);
        xd[4] = pack2(rb[kh].x, rb[kh].x);
        xd[5] = pack2(rb[kh].y, rb[kh].y);
#pragma unroll
        for (int kw = 0; kw < 3; kw++) {
            const ulonglong2* wp = reinterpret_cast<const ulonglong2*>(
                &sw[(ci * 9 + kh * 3 + kw) * 32 + co_grp * 8]);
            ulonglong2 wA = wp[0];
            ulonglong2 wB = wp[1];
            unsigned long long wq0 = wA.x, wq1 = wA.y,
                               wq2 = wB.x, wq3 = wB.y;
#pragma unroll
            for (int p = 0; p < 4; p++) {
                ffma2(acc[0][p], wq0, xd[kw + p]);
                ffma2(acc[1][p], wq1, xd[kw + p]);
                ffma2(acc[2][p], wq2, xd[kw + p]);
                ffma2(acc[3][p], wq3, xd[kw + p]);
            }
        }
    }
}

__global__ __launch_bounds__(256, 2)
void conv_lif_kernel(const float* __restrict__ x, float* __restrict__ out) {
    extern __shared__ __align__(16) float smem_dyn[];
    float* s_ab = smem_dyn + 2 * BUF_FLOATS;   // [0..127]=alpha, [128..255]=beta

    const int bid = blockIdx.x;
    const int ntiles = (bid < EXTRA_CTAS) ? 2 : 1;
    const int n_gc = ntiles * N_CHUNKS_PER_TILE;

    const int tid    = threadIdx.x;
    const int w_grp  = tid & 7;
    const int h_loc  = (tid >> 3) & 7;
    const int co_grp = tid >> 6;
    const int w0     = w_grp * 4;
    const int my_slot = 2 + (tid >> 5);        // warp-staggered: ci slots 2..9

    const unsigned smem_u32 = (unsigned)__cvta_generic_to_shared(smem_dyn);

    auto prefetch_share = [&](int gc) {
        const int tile_id = (gc >> 4) ? (bid + GRID_CTAS) : bid;
        int b, cout0, h0;
        decode_tile(tile_id, b, cout0, h0);
        const int tc = gc & 15;
        const int t  = tc >> 2;
        const int c0 = (tc & 3) * CIN_CHUNK;
        const int buf = gc & 1;
        const unsigned sx_base = smem_u32 + (unsigned)(buf * BUF_FLOATS) * 4u;
        const unsigned sw_base = sx_base + SX_FLOATS * 4u;
        const float* xb = x + (((t * BATCH + b) * CIN + c0) * (HH * WW));
        const unsigned c   = (unsigned)tid & 31u;
        const unsigned rg0 = (unsigned)tid >> 5;
#pragma unroll
        for (int k = 0; k < 20; k++) {
            unsigned rowg = rg0 + 8u * k;      // 0..159
            unsigned ci   = rowg / 10u;
            unsigned r    = rowg - ci * 10u;
            int gh = h0 - 1 + (int)r;
            bool valid = (unsigned)gh < (unsigned)HH;
            const float* src = xb + ci * (HH * WW) + (valid ? gh : 0) * WW + c;
            unsigned dst = sx_base +
                (unsigned)(ci * (SX_ROWS * SX_PITCH) + r * SX_PITCH + c + 1u) * 4u;
            cp_async4(dst, src, valid ? 4 : 0);
        }
        const float* wb = g_wT + c0 * 9 * COUT + cout0;
#pragma unroll
        for (int k = 0; k < 5; k++) {
            int e = tid + k * 256;
            if (e < SW_FLOATS / 4) {
                int co4 = e & 7;
                int rk  = e >> 3;
                unsigned dst = sw_base + (unsigned)(rk * 32 + co4 * 4) * 4u;
                cp_async16(dst, wb + rk * COUT + co4 * 4);
            }
        }
    };

    // ---- one-time init: alpha/beta -> smem, zero halo cols of both buffers ----
    for (int e = tid; e < COUT; e += 256) {
        s_ab[e]        = g_alpha[e];
        s_ab[COUT + e] = g_beta[e];
    }
    for (int e = tid; e < 2 * CIN_CHUNK * SX_ROWS * 2; e += 256) {  // 640
        int buf = e & 1;
        int q   = e >> 1;
        int col = (q & 1) ? 33 : 0;
        int rw  = q >> 1;
        int ci  = rw / SX_ROWS;
        int r   = rw - ci * SX_ROWS;
        smem_dyn[buf * BUF_FLOATS + ci * (SX_ROWS * SX_PITCH) + r * SX_PITCH + col] = 0.f;
    }

    unsigned long long acc[4][4];
#pragma unroll
    for (int cp = 0; cp < 4; cp++)
#pragma unroll
        for (int p = 0; p < 4; p++) acc[cp][p] = 0ULL;

    prefetch_share(0);
    CP_COMMIT();
    CP_WAIT_0();
    __syncthreads();

    for (int gc = 0; gc < n_gc; gc++) {
        const int buf = gc & 1;
        const float* sx = smem_dyn + buf * BUF_FLOATS;
        const float* sw = sx + SX_FLOATS;
        const bool have_next = (gc + 1 < n_gc);

        for (int ci = 0; ci < CIN_CHUNK; ci++) {
            compute_ci(sx, sw, ci, h_loc, w0, co_grp, acc);
            if (have_next && ci == my_slot) {   // warp-uniform branch
                prefetch_share(gc + 1);
                CP_COMMIT();
            }
        }

        // ---- epilogue at the end of each t-step ----
        if ((gc & 3) == 3) {
            const int tile_id = (gc >> 4) ? (bid + GRID_CTAS) : bid;
            int b, cout0, h0;
            decode_tile(tile_id, b, cout0, h0);
            const int t    = (gc >> 2) & 3;
            const int myc0 = cout0 + co_grp * 8;
            float4* mbase = g_mem + (size_t)tile_id * 8 * 256 + tid;
            float* ob = out + ((size_t)(t * BATCH + b) * COUT) * (HH * WW)
                            + (h0 + h_loc) * WW + w0;
#pragma unroll
            for (int cp = 0; cp < 4; cp++) {
                const int cl0 = 2 * cp, cl1 = 2 * cp + 1;
                const float a0 = s_ab[myc0 + cl0], b0 = s_ab[COUT + myc0 + cl0];
                const float a1 = s_ab[myc0 + cl1], b1 = s_ab[COUT + myc0 + cl1];
                float4 m0v, m1v;
                if (t > 0) {
                    m0v = mbase[cl0 * 256];
                    m1v = mbase[cl1 * 256];
                } else {
                    m0v = make_float4(0.f, 0.f, 0.f, 0.f);
                    m1v = make_float4(0.f, 0.f, 0.f, 0.f);
                }
                float* m0a = &m0v.x;
                float* m1a = &m1v.x;
                float sp0[4], sp1[4];
#pragma unroll
                for (int p = 0; p < 4; p++) {
                    float lo, hi;
                    unpack2(acc[cp][p], lo, hi);
                    float y0 = lo * a0 + b0;
                    float y1 = hi * a1 + b1;
                    float m0 = m0a[p] * TAU + y0;
                    float m1 = m1a[p] * TAU + y1;
                    float k0 = (m0 > THRESH) ? 1.f : 0.f;
                    float k1 = (m1 > THRESH) ? 1.f : 0.f;
                    m0a[p] = (k0 != 0.f) ? 0.f : m0;
                    m1a[p] = (k1 != 0.f) ? 0.f : m1;
                    sp0[p] = k0;
                    sp1[p] = k1;
                }
                stg_cs128(ob + (size_t)(myc0 + cl0) * (HH * WW),
                          make_float4(sp0[0], sp0[1], sp0[2], sp0[3]));
                stg_cs128(ob + (size_t)(myc0 + cl1) * (HH * WW),
                          make_float4(sp1[0], sp1[1], sp1[2], sp1[3]));
                if (t < T_STEPS - 1) {
                    mbase[cl0 * 256] = m0v;
                    mbase[cl1 * 256] = m1v;
                }
            }
#pragma unroll
            for (int cp = 0; cp < 4; cp++)
#pragma unroll
                for (int p = 0; p < 4; p++) acc[cp][p] = 0ULL;
        }

        if (have_next) CP_WAIT_0();
        // single barrier: publishes chunk gc+1's data AND releases buf^1 for
        // the prefetch issued during iteration gc+1.
        __syncthreads();
    }
}

extern "C" void kernel_launch(void* const* d_in, const int* in_sizes, int n_in,
                              void* d_out, int out_size) {
    (void)in_sizes; (void)n_in; (void)out_size;
    const float* x      = (const float*)d_in[0];
    const float* conv_w = (const float*)d_in[1];
    const float* conv_b = (const float*)d_in[2];
    const float* bng    = (const float*)d_in[3];
    const float* bnb    = (const float*)d_in[4];
    const float* bnm    = (const float*)d_in[5];
    const float* bnv    = (const float*)d_in[6];
    float* out = (float*)d_out;

    static int attr_done = 0;
    if (!attr_done) {
        cudaFuncSetAttribute(conv_lif_kernel,
                             cudaFuncAttributeMaxDynamicSharedMemorySize,
                             SMEM_BYTES);
        attr_done = 1;
    }

    prep_kernel<<<72, 256>>>(conv_w, conv_b, bng, bnb, bnm, bnv);

    conv_lif_kernel<<<GRID_CTAS, 256, SMEM_BYTES>>>(x, out);
}